// round 3
// baseline (speedup 1.0000x reference)
#include <cuda_runtime.h>

#define I_DIM 128
#define O_DIM 64
#define R_NUM 7
#define T_NUM 4
#define RO    (R_NUM * O_DIM)   // 448
#define N_MAX 300032

// Scratch (static device globals; no runtime allocation).
__device__ __align__(256) float g_h[(size_t)N_MAX * RO];   // ~537 MB: h[n][r*64+o]
__device__ int   g_cnt[N_MAX * R_NUM];
__device__ float g_inv[N_MAX * R_NUM];

// ---------------------------------------------------------------------------
// counts
// ---------------------------------------------------------------------------
__global__ void zero_cnt_kernel(int NR) {
    int i = blockIdx.x * blockDim.x + threadIdx.x;
    if (i < NR) g_cnt[i] = 0;
}

__global__ void count_kernel(const int* __restrict__ ei, const int* __restrict__ et, int E) {
    int e = blockIdx.x * blockDim.x + threadIdx.x;
    if (e < E) {
        int dst = ei[E + e];
        atomicAdd(&g_cnt[dst * R_NUM + et[e]], 1);
    }
}

__global__ void inv_kernel(int NR) {
    int i = blockIdx.x * blockDim.x + threadIdx.x;
    if (i < NR) {
        int c = g_cnt[i];
        g_inv[i] = (c > 0) ? (1.0f / (float)c) : 1.0f;
    }
}

// ---------------------------------------------------------------------------
// h[n][r*64+o] = sum_k x[n][k] * W_rel[r][k][o]
// Tile: 128 rows x 64 cols (one relation) x K-chunks of 32.
// 256 threads (16x16), thread tile 8x4.
// ---------------------------------------------------------------------------
#define BM 128
#define BK 32

__global__ void __launch_bounds__(256) gemm_h_kernel(const float* __restrict__ x,
                                                     const float* __restrict__ Wrel,
                                                     int N) {
    __shared__ float Xs[BM][BK];      // 16 KB
    __shared__ float Ws[BK][O_DIM];   // 8 KB

    int r  = blockIdx.y;
    int m0 = blockIdx.x * BM;
    int tid = threadIdx.x;
    int tx = tid & 15;        // 0..15 -> 4-col group
    int ty = tid >> 4;        // 0..15 -> 8-row group

    const float* Wr = Wrel + (size_t)r * I_DIM * O_DIM;

    float acc[8][4];
#pragma unroll
    for (int i = 0; i < 8; i++)
#pragma unroll
        for (int j = 0; j < 4; j++) acc[i][j] = 0.0f;

    for (int k0 = 0; k0 < I_DIM; k0 += BK) {
        // load X tile: 128x32 floats = 1024 float4, 4 per thread
#pragma unroll
        for (int l = 0; l < 4; l++) {
            int idx = tid + l * 256;
            int row = idx >> 3;
            int c4  = (idx & 7) << 2;
            float4 v = make_float4(0.f, 0.f, 0.f, 0.f);
            if (m0 + row < N)
                v = *(const float4*)(x + (size_t)(m0 + row) * I_DIM + k0 + c4);
            *(float4*)(&Xs[row][c4]) = v;
        }
        // load W tile: 32x64 floats = 512 float4, 2 per thread
#pragma unroll
        for (int l = 0; l < 2; l++) {
            int idx = tid + l * 256;
            int kk = idx >> 4;
            int c4 = (idx & 15) << 2;
            *(float4*)(&Ws[kk][c4]) = *(const float4*)(Wr + (size_t)(k0 + kk) * O_DIM + c4);
        }
        __syncthreads();

#pragma unroll
        for (int k = 0; k < BK; k++) {
            float4 bv = *(const float4*)(&Ws[k][tx << 2]);
            // stage A column (8 rows) — consecutive rows, conflict-free banks
            float a0 = Xs[ty * 8 + 0][k];
            float a1 = Xs[ty * 8 + 1][k];
            float a2 = Xs[ty * 8 + 2][k];
            float a3 = Xs[ty * 8 + 3][k];
            float a4 = Xs[ty * 8 + 4][k];
            float a5 = Xs[ty * 8 + 5][k];
            float a6 = Xs[ty * 8 + 6][k];
            float a7 = Xs[ty * 8 + 7][k];
            float av[8] = {a0, a1, a2, a3, a4, a5, a6, a7};
#pragma unroll
            for (int i = 0; i < 8; i++) {
                acc[i][0] += av[i] * bv.x;
                acc[i][1] += av[i] * bv.y;
                acc[i][2] += av[i] * bv.z;
                acc[i][3] += av[i] * bv.w;
            }
        }
        __syncthreads();
    }

#pragma unroll
    for (int i = 0; i < 8; i++) {
        int row = m0 + ty * 8 + i;
        if (row < N) {
            float4 v = make_float4(acc[i][0], acc[i][1], acc[i][2], acc[i][3]);
            *(float4*)(&g_h[(size_t)row * RO + r * O_DIM + (tx << 2)]) = v;
        }
    }
}

// ---------------------------------------------------------------------------
// out[n][o] = sum_k x[n][k] * W_root[type[n]][k][o] + b_root[type[n]][o]
// 64 nodes/block, 256 threads (16x16), thread tile 4x4. W_root stays in L1/L2.
// Also serves as the initializer of d_out (poisoned by harness).
// ---------------------------------------------------------------------------
__global__ void __launch_bounds__(256) root_kernel(const float* __restrict__ x,
                                                   const int* __restrict__ ntype,
                                                   const float* __restrict__ Wroot,
                                                   const float* __restrict__ broot,
                                                   float* __restrict__ out,
                                                   int N) {
    __shared__ float Xs[64][I_DIM];   // 32 KB
    int m0 = blockIdx.x * 64;
    int tid = threadIdx.x;
    int tx = tid & 15;
    int ty = tid >> 4;

    // load X tile: 64x128 floats = 2048 float4, 8 per thread
#pragma unroll
    for (int l = 0; l < 8; l++) {
        int idx = tid + l * 256;
        int row = idx >> 5;
        int c4  = (idx & 31) << 2;
        float4 v = make_float4(0.f, 0.f, 0.f, 0.f);
        if (m0 + row < N)
            v = *(const float4*)(x + (size_t)(m0 + row) * I_DIM + c4);
        *(float4*)(&Xs[row][c4]) = v;
    }
    __syncthreads();

    int tyi[4];
    const float* wb[4];
#pragma unroll
    for (int i = 0; i < 4; i++) {
        int row = m0 + ty * 4 + i;
        int tt = (row < N) ? ntype[row] : 0;
        tyi[i] = tt;
        wb[i] = Wroot + (size_t)tt * I_DIM * O_DIM + (tx << 2);
    }

    float acc[4][4];
#pragma unroll
    for (int i = 0; i < 4; i++)
#pragma unroll
        for (int j = 0; j < 4; j++) acc[i][j] = 0.0f;

#pragma unroll 4
    for (int k = 0; k < I_DIM; k++) {
#pragma unroll
        for (int i = 0; i < 4; i++) {
            float a = Xs[ty * 4 + i][k];
            float4 bv = *(const float4*)(wb[i] + (size_t)k * O_DIM);
            acc[i][0] += a * bv.x;
            acc[i][1] += a * bv.y;
            acc[i][2] += a * bv.z;
            acc[i][3] += a * bv.w;
        }
    }

#pragma unroll
    for (int i = 0; i < 4; i++) {
        int row = m0 + ty * 4 + i;
        if (row < N) {
            float4 bb = *(const float4*)(broot + tyi[i] * O_DIM + (tx << 2));
            float4 v = make_float4(acc[i][0] + bb.x, acc[i][1] + bb.y,
                                   acc[i][2] + bb.z, acc[i][3] + bb.w);
            *(float4*)(out + (size_t)row * O_DIM + (tx << 2)) = v;
        }
    }
}

// ---------------------------------------------------------------------------
// scatter: out[dst] += h[src, et] * inv[dst*R+et], 16 lanes per edge (float4 each)
// ---------------------------------------------------------------------------
__global__ void __launch_bounds__(256) scatter_kernel(const int* __restrict__ ei,
                                                      const int* __restrict__ et,
                                                      float* __restrict__ out,
                                                      int E) {
    long long gt = (long long)blockIdx.x * blockDim.x + threadIdx.x;
    int e = (int)(gt >> 4);
    if (e >= E) return;
    int sub = (int)(gt & 15);

    int src = ei[e];
    int dst = ei[E + e];
    int r   = et[e];
    float w = g_inv[dst * R_NUM + r];

    const float* __restrict__ hp = g_h + (size_t)src * RO + r * O_DIM + (sub << 2);
    float4 h4 = *(const float4*)hp;
    float4 v = make_float4(h4.x * w, h4.y * w, h4.z * w, h4.w * w);
    atomicAdd((float4*)(out + (size_t)dst * O_DIM + (sub << 2)), v);
}

// ---------------------------------------------------------------------------
extern "C" void kernel_launch(void* const* d_in, const int* in_sizes, int n_in,
                              void* d_out, int out_size) {
    const float* x     = (const float*)d_in[0];
    const int*   ei    = (const int*)d_in[1];
    const int*   et    = (const int*)d_in[2];
    const int*   nt    = (const int*)d_in[3];
    const float* Wrel  = (const float*)d_in[4];
    const float* Wroot = (const float*)d_in[5];
    const float* broot = (const float*)d_in[6];
    float* out = (float*)d_out;

    int N  = in_sizes[3];   // node_type length
    int E  = in_sizes[2];   // edge_type length
    int NR = N * R_NUM;

    zero_cnt_kernel<<<(NR + 255) / 256, 256>>>(NR);
    count_kernel<<<(E + 255) / 256, 256>>>(ei, et, E);
    inv_kernel<<<(NR + 255) / 256, 256>>>(NR);

    dim3 gg((N + BM - 1) / BM, R_NUM);
    gemm_h_kernel<<<gg, 256>>>(x, Wrel, N);

    root_kernel<<<(N + 63) / 64, 256>>>(x, nt, Wroot, broot, out, N);

    long long total = (long long)E * 16;
    scatter_kernel<<<(int)((total + 255) / 256), 256>>>(ei, et, out, E);
}

// round 9
// speedup vs baseline: 1.1598x; 1.1598x over previous
#include <cuda_runtime.h>
#include <cuda_bf16.h>
#include <cstdint>

#define I_DIM 128
#define O_DIM 64
#define R_NUM 7
#define T_NUM 4
#define RO    (R_NUM * O_DIM)   // 448
#define N_MAX 300032

// Scratch (static device globals; no runtime allocation).
__device__ __align__(256) float g_h[(size_t)N_MAX * RO];   // ~537 MB: h[n][r*64+o]
__device__ int   g_cnt[N_MAX * R_NUM];
__device__ float g_inv[N_MAX * R_NUM];
// W_rel transposed + bf16-split: [r][n][k]
__device__ __align__(16) __nv_bfloat16 g_WtHi[R_NUM * O_DIM * I_DIM];
__device__ __align__(16) __nv_bfloat16 g_WtLo[R_NUM * O_DIM * I_DIM];

// ---------------------------------------------------------------------------
// counts
// ---------------------------------------------------------------------------
__global__ void zero_cnt_kernel(int NR) {
    int i = blockIdx.x * blockDim.x + threadIdx.x;
    if (i < NR) g_cnt[i] = 0;
}
__global__ void count_kernel(const int* __restrict__ ei, const int* __restrict__ et, int E) {
    int e = blockIdx.x * blockDim.x + threadIdx.x;
    if (e < E) atomicAdd(&g_cnt[ei[E + e] * R_NUM + et[e]], 1);
}
__global__ void inv_kernel(int NR) {
    int i = blockIdx.x * blockDim.x + threadIdx.x;
    if (i < NR) {
        int c = g_cnt[i];
        g_inv[i] = (c > 0) ? (1.0f / (float)c) : 1.0f;
    }
}

// ---------------------------------------------------------------------------
// W_rel [r][k][n] fp32 -> transposed bf16 hi/lo [r][n][k]
// ---------------------------------------------------------------------------
__global__ void wsplit_kernel(const float* __restrict__ Wrel) {
    int idx = blockIdx.x * blockDim.x + threadIdx.x;
    if (idx >= R_NUM * I_DIM * O_DIM) return;
    int r = idx >> 13;          // /8192
    int rem = idx & 8191;
    int k = rem >> 6;           // /64
    int n = rem & 63;
    float v = Wrel[idx];
    __nv_bfloat16 hi = __float2bfloat16_rn(v);
    __nv_bfloat16 lo = __float2bfloat16_rn(v - __bfloat162float(hi));
    size_t o = ((size_t)r * O_DIM + n) * I_DIM + k;
    g_WtHi[o] = hi;
    g_WtLo[o] = lo;
}

// ---------------------------------------------------------------------------
// mma.sync h-GEMM (legacy HMMA path; compute_103-safe, no tcgen05).
// One CTA: 128 rows x 64 cols (one relation). 8 warps, warp tile 16x64.
// D = xh*Wh + xh*Wl + xl*Wh  (bf16 2-term split, fp32 accumulate)
//
// smem layout (dynamic, 96 KB):
//   Ahi[128][128] bf16 (32K) | Alo (32K) | Bhi[64][128] bf16 (16K) | Blo (16K)
// Rows are 256B; 16B chunks XOR-swizzled: chunk' = chunk ^ (row & 7)
// ---------------------------------------------------------------------------
#define SM_AHI 0
#define SM_ALO 32768
#define SM_BHI 65536
#define SM_BLO 81920
#define SM_TOTAL 98304

__device__ __forceinline__ uint32_t smem_u32(const void* p) {
    uint32_t a;
    asm("{ .reg .u64 t; cvta.to.shared.u64 t, %1; cvt.u32.u64 %0, t; }" : "=r"(a) : "l"(p));
    return a;
}
__device__ __forceinline__ void ldmx4(uint32_t& r0, uint32_t& r1, uint32_t& r2, uint32_t& r3,
                                      uint32_t addr) {
    asm volatile("ldmatrix.sync.aligned.m8n8.x4.shared.b16 {%0,%1,%2,%3}, [%4];"
                 : "=r"(r0), "=r"(r1), "=r"(r2), "=r"(r3) : "r"(addr));
}
__device__ __forceinline__ void mma_bf16(float* c, uint32_t a0, uint32_t a1, uint32_t a2,
                                         uint32_t a3, uint32_t b0, uint32_t b1) {
    asm volatile("mma.sync.aligned.m16n8k16.row.col.f32.bf16.bf16.f32 "
                 "{%0,%1,%2,%3}, {%4,%5,%6,%7}, {%8,%9}, {%0,%1,%2,%3};"
                 : "+f"(c[0]), "+f"(c[1]), "+f"(c[2]), "+f"(c[3])
                 : "r"(a0), "r"(a1), "r"(a2), "r"(a3), "r"(b0), "r"(b1));
}

__global__ void __launch_bounds__(256) gemm_h_mma(const float* __restrict__ x, int N) {
    extern __shared__ __align__(256) char smem[];
    uint32_t sb = smem_u32(smem);
    int tid  = threadIdx.x;
    int wid  = tid >> 5;
    int lane = tid & 31;
    int r    = blockIdx.y;
    int m0   = blockIdx.x * 128;

    // --- A prologue: x fp32 -> bf16 hi/lo, swizzled. 8192 pairs, 32/thread ---
#pragma unroll
    for (int l = 0; l < 32; l++) {
        int p   = tid + l * 256;
        int row = p >> 6;
        int pk  = p & 63;                 // k-pair index (k = 2*pk)
        float2 v = make_float2(0.f, 0.f);
        if (m0 + row < N)
            v = *(const float2*)(x + (size_t)(m0 + row) * I_DIM + pk * 2);
        __nv_bfloat16 hx = __float2bfloat16_rn(v.x);
        __nv_bfloat16 hy = __float2bfloat16_rn(v.y);
        __nv_bfloat16 lx = __float2bfloat16_rn(v.x - __bfloat162float(hx));
        __nv_bfloat16 ly = __float2bfloat16_rn(v.y - __bfloat162float(hy));
        __nv_bfloat162 hp = __nv_bfloat162(hx, hy);
        __nv_bfloat162 lp = __nv_bfloat162(lx, ly);
        int c = pk >> 2;                  // 16B chunk (0..15)
        uint32_t byte = (uint32_t)(row * 256 + ((c ^ (row & 7)) << 4) + (pk & 3) * 4);
        *(uint32_t*)(smem + SM_AHI + byte) = *(uint32_t*)&hp;
        *(uint32_t*)(smem + SM_ALO + byte) = *(uint32_t*)&lp;
    }
    // --- B prologue: Wt hi/lo [64][128] bf16, swizzled. 4096 pairs, 16/thread ---
    {
        const uint32_t* srcH = (const uint32_t*)(g_WtHi + (size_t)r * O_DIM * I_DIM);
        const uint32_t* srcL = (const uint32_t*)(g_WtLo + (size_t)r * O_DIM * I_DIM);
#pragma unroll
        for (int l = 0; l < 16; l++) {
            int p  = tid + l * 256;
            int n  = p >> 6;
            int pk = p & 63;
            int c  = pk >> 2;
            uint32_t byte = (uint32_t)(n * 256 + ((c ^ (n & 7)) << 4) + (pk & 3) * 4);
            *(uint32_t*)(smem + SM_BHI + byte) = srcH[p];
            *(uint32_t*)(smem + SM_BLO + byte) = srcL[p];
        }
    }
    __syncthreads();

    int mbase = wid * 16;
    float acc[8][4];
#pragma unroll
    for (int i = 0; i < 8; i++)
#pragma unroll
        for (int j = 0; j < 4; j++) acc[i][j] = 0.0f;

    const uint32_t asel[3] = {SM_AHI, SM_AHI, SM_ALO};
    const uint32_t bsel[3] = {SM_BHI, SM_BLO, SM_BHI};

    // Per-lane address components (constant across ksteps)
    int arow   = mbase + (lane & 15);
    int akhalf = lane >> 4;                            // 0/1
    int brow_n = (lane & 7) + ((lane >> 4) << 3);      // n within 16-row pair block? no:
    // lanes 0-7:   nt_even rows, klow
    // lanes 8-15:  nt_even rows, khigh
    // lanes 16-23: nt_odd  rows, klow
    // lanes 24-31: nt_odd  rows, khigh
    int b_ntoff = (lane >> 4);                         // 0 => nt 2j, 1 => nt 2j+1
    int b_khalf = (lane >> 3) & 1;
    int b_nrow  = lane & 7;

#pragma unroll
    for (int pass = 0; pass < 3; pass++) {
        uint32_t abase = sb + asel[pass];
        uint32_t bbase = sb + bsel[pass];
#pragma unroll
        for (int ks = 0; ks < 8; ks++) {
            // A fragment (16x16)
            int ac = ks * 2 + akhalf;
            uint32_t aaddr = abase + arow * 256 + ((ac ^ (arow & 7)) << 4);
            uint32_t a0, a1, a2, a3;
            ldmx4(a0, a1, a2, a3, aaddr);
            int bc = ks * 2 + b_khalf;
            // B fragments: 4 x ldmatrix.x4 covering 8 n-tiles
            uint32_t bfr[16];
#pragma unroll
            for (int j = 0; j < 4; j++) {
                int n = (2 * j + b_ntoff) * 8 + b_nrow;
                uint32_t baddr = bbase + n * 256 + ((bc ^ (n & 7)) << 4);
                ldmx4(bfr[j * 4 + 0], bfr[j * 4 + 1], bfr[j * 4 + 2], bfr[j * 4 + 3], baddr);
            }
#pragma unroll
            for (int j = 0; j < 4; j++) {
                mma_bf16(acc[2 * j + 0], a0, a1, a2, a3, bfr[j * 4 + 0], bfr[j * 4 + 1]);
                mma_bf16(acc[2 * j + 1], a0, a1, a2, a3, bfr[j * 4 + 2], bfr[j * 4 + 3]);
            }
        }
    }

    // --- epilogue: C frag -> g_h.  thread holds rows q, q+8; cols nt*8+(t%4)*2 ---
    int q  = lane >> 2;
    int tc = (lane & 3) * 2;
    int row0 = m0 + mbase + q;
    int row1 = row0 + 8;
    float* base0 = g_h + (size_t)row0 * RO + r * O_DIM + tc;
    float* base1 = g_h + (size_t)row1 * RO + r * O_DIM + tc;
#pragma unroll
    for (int nt = 0; nt < 8; nt++) {
        if (row0 < N) *(float2*)(base0 + nt * 8) = make_float2(acc[nt][0], acc[nt][1]);
        if (row1 < N) *(float2*)(base1 + nt * 8) = make_float2(acc[nt][2], acc[nt][3]);
    }
}

// ---------------------------------------------------------------------------
// root: out[n] = x[n] @ W_root[type[n]] + b_root[type[n]]   (initializes d_out)
// ---------------------------------------------------------------------------
__global__ void __launch_bounds__(256) root_kernel(const float* __restrict__ x,
                                                   const int* __restrict__ ntype,
                                                   const float* __restrict__ Wroot,
                                                   const float* __restrict__ broot,
                                                   float* __restrict__ out,
                                                   int N) {
    __shared__ float Xs[64][I_DIM];   // 32 KB
    int m0 = blockIdx.x * 64;
    int tid = threadIdx.x;
    int tx = tid & 15;
    int ty = tid >> 4;

#pragma unroll
    for (int l = 0; l < 8; l++) {
        int idx = tid + l * 256;
        int row = idx >> 5;
        int c4  = (idx & 31) << 2;
        float4 v = make_float4(0.f, 0.f, 0.f, 0.f);
        if (m0 + row < N)
            v = *(const float4*)(x + (size_t)(m0 + row) * I_DIM + c4);
        *(float4*)(&Xs[row][c4]) = v;
    }
    __syncthreads();

    int tyi[4];
    const float* wb[4];
#pragma unroll
    for (int i = 0; i < 4; i++) {
        int row = m0 + ty * 4 + i;
        int tt = (row < N) ? ntype[row] : 0;
        tyi[i] = tt;
        wb[i] = Wroot + (size_t)tt * I_DIM * O_DIM + (tx << 2);
    }

    float acc[4][4];
#pragma unroll
    for (int i = 0; i < 4; i++)
#pragma unroll
        for (int j = 0; j < 4; j++) acc[i][j] = 0.0f;

#pragma unroll 4
    for (int k = 0; k < I_DIM; k++) {
#pragma unroll
        for (int i = 0; i < 4; i++) {
            float a = Xs[ty * 4 + i][k];
            float4 bv = *(const float4*)(wb[i] + (size_t)k * O_DIM);
            acc[i][0] += a * bv.x;
            acc[i][1] += a * bv.y;
            acc[i][2] += a * bv.z;
            acc[i][3] += a * bv.w;
        }
    }

#pragma unroll
    for (int i = 0; i < 4; i++) {
        int row = m0 + ty * 4 + i;
        if (row < N) {
            float4 bb = *(const float4*)(broot + tyi[i] * O_DIM + (tx << 2));
            float4 v = make_float4(acc[i][0] + bb.x, acc[i][1] + bb.y,
                                   acc[i][2] + bb.z, acc[i][3] + bb.w);
            *(float4*)(out + (size_t)row * O_DIM + (tx << 2)) = v;
        }
    }
}

// ---------------------------------------------------------------------------
// scatter: out[dst] += h[src, et] * inv[dst*R+et], 16 lanes/edge (float4 each)
// ---------------------------------------------------------------------------
__global__ void __launch_bounds__(256) scatter_kernel(const int* __restrict__ ei,
                                                      const int* __restrict__ et,
                                                      float* __restrict__ out,
                                                      int E) {
    long long gt = (long long)blockIdx.x * blockDim.x + threadIdx.x;
    int e = (int)(gt >> 4);
    if (e >= E) return;
    int sub = (int)(gt & 15);

    int src = ei[e];
    int dst = ei[E + e];
    int r   = et[e];
    float w = g_inv[dst * R_NUM + r];

    const float* __restrict__ hp = g_h + (size_t)src * RO + r * O_DIM + (sub << 2);
    float4 h4 = *(const float4*)hp;
    float4 v = make_float4(h4.x * w, h4.y * w, h4.z * w, h4.w * w);
    atomicAdd((float4*)(out + (size_t)dst * O_DIM + (sub << 2)), v);
}

// ---------------------------------------------------------------------------
extern "C" void kernel_launch(void* const* d_in, const int* in_sizes, int n_in,
                              void* d_out, int out_size) {
    const float* x     = (const float*)d_in[0];
    const int*   ei    = (const int*)d_in[1];
    const int*   et    = (const int*)d_in[2];
    const int*   nt    = (const int*)d_in[3];
    const float* Wrel  = (const float*)d_in[4];
    const float* Wroot = (const float*)d_in[5];
    const float* broot = (const float*)d_in[6];
    float* out = (float*)d_out;

    int N  = in_sizes[3];
    int E  = in_sizes[2];
    int NR = N * R_NUM;

    static bool attr_set = false;
    if (!attr_set) {
        cudaFuncSetAttribute(gemm_h_mma, cudaFuncAttributeMaxDynamicSharedMemorySize, SM_TOTAL);
        attr_set = true;
    }

    zero_cnt_kernel<<<(NR + 255) / 256, 256>>>(NR);
    count_kernel<<<(E + 255) / 256, 256>>>(ei, et, E);
    inv_kernel<<<(NR + 255) / 256, 256>>>(NR);

    wsplit_kernel<<<(R_NUM * I_DIM * O_DIM + 255) / 256, 256>>>(Wrel);

    dim3 gg((N + 127) / 128, R_NUM);
    gemm_h_mma<<<gg, 256, SM_TOTAL>>>(x, N);

    root_kernel<<<(N + 63) / 64, 256>>>(x, nt, Wroot, broot, out, N);

    long long total = (long long)E * 16;
    scatter_kernel<<<(int)((total + 255) / 256), 256>>>(ei, et, out, E);
}

// round 10
// speedup vs baseline: 1.6939x; 1.4606x over previous
#include <cuda_runtime.h>
#include <cuda_bf16.h>
#include <cstdint>

#define I_DIM 128
#define O_DIM 64
#define R_NUM 7
#define T_NUM 4
#define SEG_NUM (R_NUM + T_NUM)   // 11: 7 relations + 4 root node-types
#define RO    (R_NUM * O_DIM)     // 448
#define N_MAX 300032

// Scratch (static device globals; no runtime allocation).
__device__ __align__(256) float g_h[(size_t)N_MAX * RO];   // ~537 MB: h[n][r*64+o]
__device__ int   g_cnt[N_MAX * R_NUM];
__device__ float g_inv[N_MAX * R_NUM];
// W (rel 0..6, root-type 7..10) transposed + bf16-split: [seg][n][k]
__device__ __align__(16) __nv_bfloat16 g_WtHi[SEG_NUM * O_DIM * I_DIM];
__device__ __align__(16) __nv_bfloat16 g_WtLo[SEG_NUM * O_DIM * I_DIM];

// ---------------------------------------------------------------------------
// counts
// ---------------------------------------------------------------------------
__global__ void zero_cnt_kernel(int NR) {
    int i = blockIdx.x * blockDim.x + threadIdx.x;
    if (i < NR) g_cnt[i] = 0;
}
__global__ void count_kernel(const int* __restrict__ ei, const int* __restrict__ et, int E) {
    int e = blockIdx.x * blockDim.x + threadIdx.x;
    if (e < E) atomicAdd(&g_cnt[ei[E + e] * R_NUM + et[e]], 1);
}
__global__ void inv_kernel(int NR) {
    int i = blockIdx.x * blockDim.x + threadIdx.x;
    if (i < NR) {
        int c = g_cnt[i];
        g_inv[i] = (c > 0) ? (1.0f / (float)c) : 1.0f;
    }
}

// ---------------------------------------------------------------------------
// W_rel [r][k][n] and W_root [t][k][n] fp32 -> transposed bf16 hi/lo [seg][n][k]
// ---------------------------------------------------------------------------
__global__ void wsplit_kernel(const float* __restrict__ Wrel,
                              const float* __restrict__ Wroot) {
    int idx = blockIdx.x * blockDim.x + threadIdx.x;
    if (idx >= SEG_NUM * I_DIM * O_DIM) return;
    int seg = idx >> 13;          // /8192
    int rem = idx & 8191;
    int k = rem >> 6;             // /64
    int n = rem & 63;
    float v = (seg < R_NUM) ? Wrel[idx]
                            : Wroot[(size_t)(seg - R_NUM) * 8192 + rem];
    __nv_bfloat16 hi = __float2bfloat16_rn(v);
    __nv_bfloat16 lo = __float2bfloat16_rn(v - __bfloat162float(hi));
    size_t o = ((size_t)seg * O_DIM + n) * I_DIM + k;
    g_WtHi[o] = hi;
    g_WtLo[o] = lo;
}

// ---------------------------------------------------------------------------
// Fused mma.sync GEMM: one CTA = 128 rows x (7 relations -> g_h, 4 types -> out)
// D = xh*Wh + xh*Wl + xl*Wh  (bf16 2-term split, fp32 accumulate)
//
// smem (dynamic, 130.5 KB):
//   Ahi 32K | Alo 32K | B0hi 16K | B0lo 16K | B1hi 16K | B1lo 16K | NT 512 | BR 1K
// Rows are 256B; 16B chunks XOR-swizzled: chunk' = chunk ^ (row & 7)
// ---------------------------------------------------------------------------
#define SM_AHI 0
#define SM_ALO 32768
#define SM_B0H 65536
#define SM_B0L 81920
#define SM_B1H 98304
#define SM_B1L 114688
#define SM_NT  131072
#define SM_BR  131584
#define SM_TOTAL 132608

__device__ __forceinline__ uint32_t smem_u32(const void* p) {
    uint32_t a;
    asm("{ .reg .u64 t; cvta.to.shared.u64 t, %1; cvt.u32.u64 %0, t; }" : "=r"(a) : "l"(p));
    return a;
}
__device__ __forceinline__ void ldmx4(uint32_t& r0, uint32_t& r1, uint32_t& r2, uint32_t& r3,
                                      uint32_t addr) {
    asm volatile("ldmatrix.sync.aligned.m8n8.x4.shared.b16 {%0,%1,%2,%3}, [%4];"
                 : "=r"(r0), "=r"(r1), "=r"(r2), "=r"(r3) : "r"(addr));
}
__device__ __forceinline__ void mma_bf16(float* c, uint32_t a0, uint32_t a1, uint32_t a2,
                                         uint32_t a3, uint32_t b0, uint32_t b1) {
    asm volatile("mma.sync.aligned.m16n8k16.row.col.f32.bf16.bf16.f32 "
                 "{%0,%1,%2,%3}, {%4,%5,%6,%7}, {%8,%9}, {%0,%1,%2,%3};"
                 : "+f"(c[0]), "+f"(c[1]), "+f"(c[2]), "+f"(c[3])
                 : "r"(a0), "r"(a1), "r"(a2), "r"(a3), "r"(b0), "r"(b1));
}
__device__ __forceinline__ void cpa16(uint32_t dst, const void* src) {
    asm volatile("cp.async.cg.shared.global [%0], [%1], 16;" :: "r"(dst), "l"(src) : "memory");
}
__device__ __forceinline__ void cpa_commit() { asm volatile("cp.async.commit_group;" ::: "memory"); }
__device__ __forceinline__ void cpa_wait1()  { asm volatile("cp.async.wait_group 1;" ::: "memory"); }
__device__ __forceinline__ void cpa_wait0()  { asm volatile("cp.async.wait_group 0;" ::: "memory"); }

// prefetch one segment's B (hi+lo, 64x128 bf16 each) into a buffer, swizzled
__device__ __forceinline__ void prefetch_B(char* smem, uint32_t sb, int seg,
                                           uint32_t offH, uint32_t offL, int tid) {
    const char* srcH = (const char*)(g_WtHi + (size_t)seg * O_DIM * I_DIM);
    const char* srcL = (const char*)(g_WtLo + (size_t)seg * O_DIM * I_DIM);
#pragma unroll
    for (int l = 0; l < 4; l++) {
        int p = tid + l * 256;          // 16B-chunk id 0..1023
        int n = p >> 4;
        int c = p & 15;
        uint32_t dst = (uint32_t)(n * 256 + ((c ^ (n & 7)) << 4));
        cpa16(sb + offH + dst, srcH + p * 16);
        cpa16(sb + offL + dst, srcL + p * 16);
    }
}

__global__ void __launch_bounds__(256) gemm_fused(const float* __restrict__ x,
                                                  const int* __restrict__ ntype,
                                                  const float* __restrict__ broot,
                                                  float* __restrict__ out,
                                                  int N) {
    extern __shared__ __align__(256) char smem[];
    uint32_t sb = smem_u32(smem);
    int tid  = threadIdx.x;
    int wid  = tid >> 5;
    int lane = tid & 31;
    int m0   = blockIdx.x * 128;

    // kick off B prefetch for segments 0 and 1 first (overlap with A convert)
    prefetch_B(smem, sb, 0, SM_B0H, SM_B0L, tid);
    cpa_commit();
    prefetch_B(smem, sb, 1, SM_B1H, SM_B1L, tid);
    cpa_commit();

    // --- A prologue: x fp32 -> bf16 hi/lo, swizzled. 8192 pairs, 32/thread ---
#pragma unroll
    for (int l = 0; l < 32; l++) {
        int p   = tid + l * 256;
        int row = p >> 6;
        int pk  = p & 63;                 // k-pair index (k = 2*pk)
        float2 v = make_float2(0.f, 0.f);
        if (m0 + row < N)
            v = *(const float2*)(x + (size_t)(m0 + row) * I_DIM + pk * 2);
        __nv_bfloat16 hx = __float2bfloat16_rn(v.x);
        __nv_bfloat16 hy = __float2bfloat16_rn(v.y);
        __nv_bfloat16 lx = __float2bfloat16_rn(v.x - __bfloat162float(hx));
        __nv_bfloat16 ly = __float2bfloat16_rn(v.y - __bfloat162float(hy));
        __nv_bfloat162 hp = __nv_bfloat162(hx, hy);
        __nv_bfloat162 lp = __nv_bfloat162(lx, ly);
        int c = pk >> 2;                  // 16B chunk (0..15)
        uint32_t byte = (uint32_t)(row * 256 + ((c ^ (row & 7)) << 4) + (pk & 3) * 4);
        *(uint32_t*)(smem + SM_AHI + byte) = *(uint32_t*)&hp;
        *(uint32_t*)(smem + SM_ALO + byte) = *(uint32_t*)&lp;
    }
    // node types + root bias into smem
    if (tid < 128) {
        int row = m0 + tid;
        ((int*)(smem + SM_NT))[tid] = (row < N) ? ntype[row] : -1;
    }
    ((float*)(smem + SM_BR))[tid] = broot[tid];   // 256 = T_NUM*O_DIM
    __syncthreads();

    // per-lane constant address components
    int mbase   = wid * 16;
    int arow    = mbase + (lane & 15);
    int akhalf  = lane >> 4;
    int b_ntoff = lane >> 4;
    int b_khalf = (lane >> 3) & 1;
    int b_nrow  = lane & 7;
    uint32_t aH_rowbase = sb + SM_AHI + arow * 256;
    uint32_t aL_rowbase = sb + SM_ALO + arow * 256;
    int asw = arow & 7;

    const int* sNT = (const int*)(smem + SM_NT);
    const float* sBR = (const float*)(smem + SM_BR);

    int q  = lane >> 2;
    int tc = (lane & 3) * 2;
    int lr0 = mbase + q;
    int lr1 = lr0 + 8;
    int row0 = m0 + lr0;
    int row1 = m0 + lr1;

    for (int s = 0; s < SEG_NUM; s++) {
        if (s < SEG_NUM - 1) cpa_wait1(); else cpa_wait0();
        __syncthreads();                       // buffer s visible to all

        uint32_t bH = sb + ((s & 1) ? SM_B1H : SM_B0H);
        uint32_t bL = sb + ((s & 1) ? SM_B1L : SM_B0L);

        float acc[8][4];
#pragma unroll
        for (int i = 0; i < 8; i++)
#pragma unroll
            for (int j = 0; j < 4; j++) acc[i][j] = 0.0f;

#pragma unroll
        for (int ks = 0; ks < 8; ks++) {
            int ac = ks * 2 + akhalf;
            uint32_t aoff = (uint32_t)((ac ^ asw) << 4);
            uint32_t ah0, ah1, ah2, ah3, al0, al1, al2, al3;
            ldmx4(ah0, ah1, ah2, ah3, aH_rowbase + aoff);
            ldmx4(al0, al1, al2, al3, aL_rowbase + aoff);

            int bc = ks * 2 + b_khalf;
            uint32_t bh[16], bl[16];
#pragma unroll
            for (int j = 0; j < 4; j++) {
                int n = (2 * j + b_ntoff) * 8 + b_nrow;
                uint32_t boff = (uint32_t)(n * 256 + ((bc ^ (n & 7)) << 4));
                ldmx4(bh[j * 4 + 0], bh[j * 4 + 1], bh[j * 4 + 2], bh[j * 4 + 3], bH + boff);
                ldmx4(bl[j * 4 + 0], bl[j * 4 + 1], bl[j * 4 + 2], bl[j * 4 + 3], bL + boff);
            }
#pragma unroll
            for (int j = 0; j < 4; j++) {
                // pass hi*hi
                mma_bf16(acc[2 * j + 0], ah0, ah1, ah2, ah3, bh[j * 4 + 0], bh[j * 4 + 1]);
                mma_bf16(acc[2 * j + 1], ah0, ah1, ah2, ah3, bh[j * 4 + 2], bh[j * 4 + 3]);
                // pass hi*lo
                mma_bf16(acc[2 * j + 0], ah0, ah1, ah2, ah3, bl[j * 4 + 0], bl[j * 4 + 1]);
                mma_bf16(acc[2 * j + 1], ah0, ah1, ah2, ah3, bl[j * 4 + 2], bl[j * 4 + 3]);
                // pass lo*hi
                mma_bf16(acc[2 * j + 0], al0, al1, al2, al3, bh[j * 4 + 0], bh[j * 4 + 1]);
                mma_bf16(acc[2 * j + 1], al0, al1, al2, al3, bh[j * 4 + 2], bh[j * 4 + 3]);
            }
        }
        __syncthreads();                       // done reading buf[s&1]
        if (s + 2 < SEG_NUM) {
            prefetch_B(smem, sb, s + 2, (s & 1) ? SM_B1H : SM_B0H,
                       (s & 1) ? SM_B1L : SM_B0L, tid);
            cpa_commit();
        }

        // --- epilogue for this segment ---
        if (s < R_NUM) {
            float* base0 = g_h + (size_t)row0 * RO + s * O_DIM + tc;
            float* base1 = g_h + (size_t)row1 * RO + s * O_DIM + tc;
#pragma unroll
            for (int nt = 0; nt < 8; nt++) {
                if (row0 < N) *(float2*)(base0 + nt * 8) = make_float2(acc[nt][0], acc[nt][1]);
                if (row1 < N) *(float2*)(base1 + nt * 8) = make_float2(acc[nt][2], acc[nt][3]);
            }
        } else {
            int t = s - R_NUM;
            const float* br = sBR + t * O_DIM + tc;
            if (row0 < N && sNT[lr0] == t) {
                float* o0 = out + (size_t)row0 * O_DIM + tc;
#pragma unroll
                for (int nt = 0; nt < 8; nt++)
                    *(float2*)(o0 + nt * 8) = make_float2(acc[nt][0] + br[nt * 8],
                                                          acc[nt][1] + br[nt * 8 + 1]);
            }
            if (row1 < N && sNT[lr1] == t) {
                float* o1 = out + (size_t)row1 * O_DIM + tc;
#pragma unroll
                for (int nt = 0; nt < 8; nt++)
                    *(float2*)(o1 + nt * 8) = make_float2(acc[nt][2] + br[nt * 8],
                                                          acc[nt][3] + br[nt * 8 + 1]);
            }
        }
    }
}

// ---------------------------------------------------------------------------
// scatter: out[dst] += h[src, et] * inv[dst*R+et], 16 lanes/edge (float4 each)
// ---------------------------------------------------------------------------
__global__ void __launch_bounds__(256) scatter_kernel(const int* __restrict__ ei,
                                                      const int* __restrict__ et,
                                                      float* __restrict__ out,
                                                      int E) {
    long long gt = (long long)blockIdx.x * blockDim.x + threadIdx.x;
    int e = (int)(gt >> 4);
    if (e >= E) return;
    int sub = (int)(gt & 15);

    int src = ei[e];
    int dst = ei[E + e];
    int r   = et[e];
    float w = g_inv[dst * R_NUM + r];

    const float* __restrict__ hp = g_h + (size_t)src * RO + r * O_DIM + (sub << 2);
    float4 h4 = *(const float4*)hp;
    float4 v = make_float4(h4.x * w, h4.y * w, h4.z * w, h4.w * w);
    atomicAdd((float4*)(out + (size_t)dst * O_DIM + (sub << 2)), v);
}

// ---------------------------------------------------------------------------
extern "C" void kernel_launch(void* const* d_in, const int* in_sizes, int n_in,
                              void* d_out, int out_size) {
    const float* x     = (const float*)d_in[0];
    const int*   ei    = (const int*)d_in[1];
    const int*   et    = (const int*)d_in[2];
    const int*   nt    = (const int*)d_in[3];
    const float* Wrel  = (const float*)d_in[4];
    const float* Wroot = (const float*)d_in[5];
    const float* broot = (const float*)d_in[6];
    float* out = (float*)d_out;

    int N  = in_sizes[3];
    int E  = in_sizes[2];
    int NR = N * R_NUM;

    static bool attr_set = false;
    if (!attr_set) {
        cudaFuncSetAttribute(gemm_fused, cudaFuncAttributeMaxDynamicSharedMemorySize, SM_TOTAL);
        attr_set = true;
    }

    zero_cnt_kernel<<<(NR + 255) / 256, 256>>>(NR);
    count_kernel<<<(E + 255) / 256, 256>>>(ei, et, E);
    inv_kernel<<<(NR + 255) / 256, 256>>>(NR);

    wsplit_kernel<<<(SEG_NUM * I_DIM * O_DIM + 255) / 256, 256>>>(Wrel, Wroot);

    gemm_fused<<<(N + 127) / 128, 256, SM_TOTAL>>>(x, nt, broot, out, N);

    long long total = (long long)E * 16;
    scatter_kernel<<<(int)((total + 255) / 256), 256>>>(ei, et, out, E);
}

// round 12
// speedup vs baseline: 1.9704x; 1.1632x over previous
#include <cuda_runtime.h>
#include <cuda_bf16.h>
#include <cstdint>

#define I_DIM 128
#define O_DIM 64
#define R_NUM 7
#define T_NUM 4
#define SEG_NUM (R_NUM + T_NUM)   // 11: 7 relations + 4 root node-types
#define RO    (R_NUM * O_DIM)     // 448
#define N_MAX 300032

// Scratch (static device globals; no runtime allocation).
__device__ __align__(256) float g_h[(size_t)N_MAX * RO];   // ~537 MB: h[n][r*64+o]
__device__ int   g_cnt[N_MAX * R_NUM];
__device__ float g_inv[N_MAX * R_NUM];
// W (rel 0..6, root-type 7..10) transposed + bf16-split: [seg][n][k]
__device__ __align__(16) __nv_bfloat16 g_WtHi[SEG_NUM * O_DIM * I_DIM];
__device__ __align__(16) __nv_bfloat16 g_WtLo[SEG_NUM * O_DIM * I_DIM];

// ---------------------------------------------------------------------------
// counts
// ---------------------------------------------------------------------------
__global__ void zero_cnt_kernel(int NR) {
    int i = blockIdx.x * blockDim.x + threadIdx.x;
    if (i < NR) g_cnt[i] = 0;
}
__global__ void count_kernel(const int* __restrict__ ei, const int* __restrict__ et, int E) {
    int e = blockIdx.x * blockDim.x + threadIdx.x;
    if (e < E) atomicAdd(&g_cnt[ei[E + e] * R_NUM + et[e]], 1);
}
__global__ void inv_kernel(int NR) {
    int i = blockIdx.x * blockDim.x + threadIdx.x;
    if (i < NR) {
        int c = g_cnt[i];
        g_inv[i] = (c > 0) ? (1.0f / (float)c) : 1.0f;
    }
}

// ---------------------------------------------------------------------------
// W_rel [r][k][n] and W_root [t][k][n] fp32 -> transposed bf16 hi/lo [seg][n][k]
// ---------------------------------------------------------------------------
__global__ void wsplit_kernel(const float* __restrict__ Wrel,
                              const float* __restrict__ Wroot) {
    int idx = blockIdx.x * blockDim.x + threadIdx.x;
    if (idx >= SEG_NUM * I_DIM * O_DIM) return;
    int seg = idx >> 13;          // /8192
    int rem = idx & 8191;
    int k = rem >> 6;             // /64
    int n = rem & 63;
    float v = (seg < R_NUM) ? Wrel[idx]
                            : Wroot[(size_t)(seg - R_NUM) * 8192 + rem];
    __nv_bfloat16 hi = __float2bfloat16_rn(v);
    __nv_bfloat16 lo = __float2bfloat16_rn(v - __bfloat162float(hi));
    size_t o = ((size_t)seg * O_DIM + n) * I_DIM + k;
    g_WtHi[o] = hi;
    g_WtLo[o] = lo;
}

// ---------------------------------------------------------------------------
// Fused mma.sync GEMM: one CTA = 128 rows x (7 relations -> g_h, 4 types -> out)
// D = xh*Wh + xh*Wl + xl*Wh  (bf16 2-term split, fp32 accumulate)
// Warp tiling: 4 M-warps x 2 N-warps, warp tile 32x32.
// Single B buffer (prefetch next segment after post-MMA sync) -> 97.5 KB smem
// -> 2 CTAs/SM.
// Rows are 256B; 16B chunks XOR-swizzled: chunk' = chunk ^ (row & 7)
// ---------------------------------------------------------------------------
#define SM_AHI 0
#define SM_ALO 32768
#define SM_BH  65536
#define SM_BL  81920
#define SM_NT  98304
#define SM_BR  98816
#define SM_TOTAL 99840

__device__ __forceinline__ uint32_t smem_u32(const void* p) {
    uint32_t a;
    asm("{ .reg .u64 t; cvta.to.shared.u64 t, %1; cvt.u32.u64 %0, t; }" : "=r"(a) : "l"(p));
    return a;
}
__device__ __forceinline__ void ldmx4(uint32_t& r0, uint32_t& r1, uint32_t& r2, uint32_t& r3,
                                      uint32_t addr) {
    asm volatile("ldmatrix.sync.aligned.m8n8.x4.shared.b16 {%0,%1,%2,%3}, [%4];"
                 : "=r"(r0), "=r"(r1), "=r"(r2), "=r"(r3) : "r"(addr));
}
__device__ __forceinline__ void mma_bf16(float* c, uint32_t a0, uint32_t a1, uint32_t a2,
                                         uint32_t a3, uint32_t b0, uint32_t b1) {
    asm volatile("mma.sync.aligned.m16n8k16.row.col.f32.bf16.bf16.f32 "
                 "{%0,%1,%2,%3}, {%4,%5,%6,%7}, {%8,%9}, {%0,%1,%2,%3};"
                 : "+f"(c[0]), "+f"(c[1]), "+f"(c[2]), "+f"(c[3])
                 : "r"(a0), "r"(a1), "r"(a2), "r"(a3), "r"(b0), "r"(b1));
}
__device__ __forceinline__ void cpa16(uint32_t dst, const void* src) {
    asm volatile("cp.async.cg.shared.global [%0], [%1], 16;" :: "r"(dst), "l"(src) : "memory");
}
__device__ __forceinline__ void cpa_commit() { asm volatile("cp.async.commit_group;" ::: "memory"); }
__device__ __forceinline__ void cpa_wait0()  { asm volatile("cp.async.wait_group 0;" ::: "memory"); }

// prefetch one segment's B (hi+lo, 64x128 bf16 each) into the single buffer
__device__ __forceinline__ void prefetch_B(uint32_t sb, int seg, int tid) {
    const char* srcH = (const char*)(g_WtHi + (size_t)seg * O_DIM * I_DIM);
    const char* srcL = (const char*)(g_WtLo + (size_t)seg * O_DIM * I_DIM);
#pragma unroll
    for (int l = 0; l < 4; l++) {
        int p = tid + l * 256;          // 16B-chunk id 0..1023
        int n = p >> 4;
        int c = p & 15;
        uint32_t dst = (uint32_t)(n * 256 + ((c ^ (n & 7)) << 4));
        cpa16(sb + SM_BH + dst, srcH + p * 16);
        cpa16(sb + SM_BL + dst, srcL + p * 16);
    }
}

__global__ void __launch_bounds__(256, 2) gemm_fused(const float* __restrict__ x,
                                                     const int* __restrict__ ntype,
                                                     const float* __restrict__ broot,
                                                     float* __restrict__ out,
                                                     int N) {
    extern __shared__ __align__(256) char smem[];
    uint32_t sb = smem_u32(smem);
    int tid  = threadIdx.x;
    int wid  = tid >> 5;
    int lane = tid & 31;
    int m0   = blockIdx.x * 128;

    // kick off B prefetch for segment 0 (overlaps with A convert)
    prefetch_B(sb, 0, tid);
    cpa_commit();

    // --- A prologue: x fp32 -> bf16 hi/lo, swizzled. 8192 pairs, 32/thread ---
#pragma unroll
    for (int l = 0; l < 32; l++) {
        int p   = tid + l * 256;
        int row = p >> 6;
        int pk  = p & 63;                 // k-pair index (k = 2*pk)
        float2 v = make_float2(0.f, 0.f);
        if (m0 + row < N)
            v = *(const float2*)(x + (size_t)(m0 + row) * I_DIM + pk * 2);
        __nv_bfloat16 hx = __float2bfloat16_rn(v.x);
        __nv_bfloat16 hy = __float2bfloat16_rn(v.y);
        __nv_bfloat16 lx = __float2bfloat16_rn(v.x - __bfloat162float(hx));
        __nv_bfloat16 ly = __float2bfloat16_rn(v.y - __bfloat162float(hy));
        __nv_bfloat162 hp = __nv_bfloat162(hx, hy);
        __nv_bfloat162 lp = __nv_bfloat162(lx, ly);
        int c = pk >> 2;                  // 16B chunk (0..15)
        uint32_t byte = (uint32_t)(row * 256 + ((c ^ (row & 7)) << 4) + (pk & 3) * 4);
        *(uint32_t*)(smem + SM_AHI + byte) = *(uint32_t*)&hp;
        *(uint32_t*)(smem + SM_ALO + byte) = *(uint32_t*)&lp;
    }
    // node types + root bias into smem
    if (tid < 128) {
        int row = m0 + tid;
        ((int*)(smem + SM_NT))[tid] = (row < N) ? ntype[row] : -1;
    }
    ((float*)(smem + SM_BR))[tid] = broot[tid];   // 256 = T_NUM*O_DIM
    __syncthreads();

    // warp tiling: wm = M strip (32 rows), wn = N strip (32 cols)
    int wm = wid & 3;
    int wn = wid >> 2;

    // A fragment addressing (two m16 tiles per warp)
    int ar0 = wm * 32 + (lane & 15);
    int ar1 = ar0 + 16;
    int akhalf = lane >> 4;
    uint32_t aH0 = sb + SM_AHI + ar0 * 256;
    uint32_t aH1 = sb + SM_AHI + ar1 * 256;
    uint32_t aL0 = sb + SM_ALO + ar0 * 256;
    uint32_t aL1 = sb + SM_ALO + ar1 * 256;
    int asw0 = ar0 & 7, asw1 = ar1 & 7;

    // B fragment addressing (two k16xn16 blocks per warp)
    int b_ntoff = lane >> 4;
    int b_khalf = (lane >> 3) & 1;
    int b_nrow  = lane & 7;
    int bn0 = wn * 32 + b_ntoff * 8 + b_nrow;        // j=0 block
    int bn1 = bn0 + 16;                              // j=1 block

    const int* sNT = (const int*)(smem + SM_NT);
    const float* sBR = (const float*)(smem + SM_BR);

    int q  = lane >> 2;
    int tc = (lane & 3) * 2;

    for (int s = 0; s < SEG_NUM; s++) {
        cpa_wait0();
        __syncthreads();                       // B[s] (and A on s=0) visible

        float acc[2][4][4];
#pragma unroll
        for (int mt = 0; mt < 2; mt++)
#pragma unroll
            for (int i = 0; i < 4; i++)
#pragma unroll
                for (int j = 0; j < 4; j++) acc[mt][i][j] = 0.0f;

#pragma unroll
        for (int ks = 0; ks < 8; ks++) {
            int ac = ks * 2 + akhalf;
            uint32_t ah[8], al[8];
            ldmx4(ah[0], ah[1], ah[2], ah[3], aH0 + (uint32_t)((ac ^ asw0) << 4));
            ldmx4(ah[4], ah[5], ah[6], ah[7], aH1 + (uint32_t)((ac ^ asw1) << 4));
            ldmx4(al[0], al[1], al[2], al[3], aL0 + (uint32_t)((ac ^ asw0) << 4));
            ldmx4(al[4], al[5], al[6], al[7], aL1 + (uint32_t)((ac ^ asw1) << 4));

            int bc = ks * 2 + b_khalf;
            uint32_t bh[8], bl[8];
            {
                uint32_t o0 = (uint32_t)(bn0 * 256 + ((bc ^ (bn0 & 7)) << 4));
                uint32_t o1 = (uint32_t)(bn1 * 256 + ((bc ^ (bn1 & 7)) << 4));
                ldmx4(bh[0], bh[1], bh[2], bh[3], sb + SM_BH + o0);
                ldmx4(bh[4], bh[5], bh[6], bh[7], sb + SM_BH + o1);
                ldmx4(bl[0], bl[1], bl[2], bl[3], sb + SM_BL + o0);
                ldmx4(bl[4], bl[5], bl[6], bl[7], sb + SM_BL + o1);
            }
#pragma unroll
            for (int mt = 0; mt < 2; mt++) {
                uint32_t* a_h = ah + mt * 4;
                uint32_t* a_l = al + mt * 4;
#pragma unroll
                for (int j = 0; j < 2; j++) {
                    uint32_t* b_h = bh + j * 4;
                    uint32_t* b_l = bl + j * 4;
                    // hi*hi
                    mma_bf16(acc[mt][2 * j + 0], a_h[0], a_h[1], a_h[2], a_h[3], b_h[0], b_h[1]);
                    mma_bf16(acc[mt][2 * j + 1], a_h[0], a_h[1], a_h[2], a_h[3], b_h[2], b_h[3]);
                    // hi*lo
                    mma_bf16(acc[mt][2 * j + 0], a_h[0], a_h[1], a_h[2], a_h[3], b_l[0], b_l[1]);
                    mma_bf16(acc[mt][2 * j + 1], a_h[0], a_h[1], a_h[2], a_h[3], b_l[2], b_l[3]);
                    // lo*hi
                    mma_bf16(acc[mt][2 * j + 0], a_l[0], a_l[1], a_l[2], a_l[3], b_h[0], b_h[1]);
                    mma_bf16(acc[mt][2 * j + 1], a_l[0], a_l[1], a_l[2], a_l[3], b_h[2], b_h[3]);
                }
            }
        }
        __syncthreads();                       // all warps done reading B buffer
        if (s + 1 < SEG_NUM) {
            prefetch_B(sb, s + 1, tid);
            cpa_commit();
        }

        // --- epilogue for this segment ---
#pragma unroll
        for (int mt = 0; mt < 2; mt++) {
            int lr0 = wm * 32 + mt * 16 + q;
            int lr1 = lr0 + 8;
            int row0 = m0 + lr0;
            int row1 = m0 + lr1;
            if (s < R_NUM) {
                float* base0 = g_h + (size_t)row0 * RO + s * O_DIM + wn * 32 + tc;
                float* base1 = g_h + (size_t)row1 * RO + s * O_DIM + wn * 32 + tc;
#pragma unroll
                for (int nt = 0; nt < 4; nt++) {
                    if (row0 < N)
                        __stcs((float2*)(base0 + nt * 8),
                               make_float2(acc[mt][nt][0], acc[mt][nt][1]));
                    if (row1 < N)
                        __stcs((float2*)(base1 + nt * 8),
                               make_float2(acc[mt][nt][2], acc[mt][nt][3]));
                }
            } else {
                int t = s - R_NUM;
                const float* br = sBR + t * O_DIM + wn * 32 + tc;
                if (row0 < N && sNT[lr0] == t) {
                    float* o0 = out + (size_t)row0 * O_DIM + wn * 32 + tc;
#pragma unroll
                    for (int nt = 0; nt < 4; nt++)
                        *(float2*)(o0 + nt * 8) = make_float2(acc[mt][nt][0] + br[nt * 8],
                                                              acc[mt][nt][1] + br[nt * 8 + 1]);
                }
                if (row1 < N && sNT[lr1] == t) {
                    float* o1 = out + (size_t)row1 * O_DIM + wn * 32 + tc;
#pragma unroll
                    for (int nt = 0; nt < 4; nt++)
                        *(float2*)(o1 + nt * 8) = make_float2(acc[mt][nt][2] + br[nt * 8],
                                                              acc[mt][nt][3] + br[nt * 8 + 1]);
                }
            }
        }
    }
}

// ---------------------------------------------------------------------------
// scatter: out[dst] += h[src, et] * inv[dst*R+et], 16 lanes/edge (float4 each)
// ---------------------------------------------------------------------------
__global__ void __launch_bounds__(256) scatter_kernel(const int* __restrict__ ei,
                                                      const int* __restrict__ et,
                                                      float* __restrict__ out,
                                                      int E) {
    long long gt = (long long)blockIdx.x * blockDim.x + threadIdx.x;
    int e = (int)(gt >> 4);
    if (e >= E) return;
    int sub = (int)(gt & 15);

    int src = ei[e];
    int dst = ei[E + e];
    int r   = et[e];
    float w = g_inv[dst * R_NUM + r];

    const float* hp = g_h + (size_t)src * RO + r * O_DIM + (sub << 2);
    float4 h4 = __ldcs((const float4*)hp);
    float4 v = make_float4(h4.x * w, h4.y * w, h4.z * w, h4.w * w);
    atomicAdd((float4*)(out + (size_t)dst * O_DIM + (sub << 2)), v);
}

// ---------------------------------------------------------------------------
extern "C" void kernel_launch(void* const* d_in, const int* in_sizes, int n_in,
                              void* d_out, int out_size) {
    const float* x     = (const float*)d_in[0];
    const int*   ei    = (const int*)d_in[1];
    const int*   et    = (const int*)d_in[2];
    const int*   nt    = (const int*)d_in[3];
    const float* Wrel  = (const float*)d_in[4];
    const float* Wroot = (const float*)d_in[5];
    const float* broot = (const float*)d_in[6];
    float* out = (float*)d_out;

    int N  = in_sizes[3];
    int E  = in_sizes[2];
    int NR = N * R_NUM;

    static bool attr_set = false;
    if (!attr_set) {
        cudaFuncSetAttribute(gemm_fused, cudaFuncAttributeMaxDynamicSharedMemorySize, SM_TOTAL);
        attr_set = true;
    }

    zero_cnt_kernel<<<(NR + 255) / 256, 256>>>(NR);
    count_kernel<<<(E + 255) / 256, 256>>>(ei, et, E);
    inv_kernel<<<(NR + 255) / 256, 256>>>(NR);

    wsplit_kernel<<<(SEG_NUM * I_DIM * O_DIM + 255) / 256, 256>>>(Wrel, Wroot);

    gemm_fused<<<(N + 127) / 128, 256, SM_TOTAL>>>(x, nt, broot, out, N);

    long long total = (long long)E * 16;
    scatter_kernel<<<(int)((total + 255) / 256), 256>>>(ei, et, out, E);
}